// round 2
// baseline (speedup 1.0000x reference)
#include <cuda_runtime.h>
#include <math.h>

// Problem constants
#define BB   16
#define CC   512
#define CBOT 64
#define NN   4096   // 64*64
#define NTILE 32    // NN/128 n-tiles (= logits partials per batch)

// ---------------------------------------------------------------------------
// Scratch (static __device__ arrays — no runtime allocation)
// ---------------------------------------------------------------------------
__device__ float g_v[BB * CBOT * NN];               // 16 MB
__device__ float g_lp[BB * NTILE * CBOT * CBOT];    // partial logits, 8 MB
__device__ float g_M[BB * CC * CBOT];               // gamma * (w_o @ attn), 2 MB

// ---------------------------------------------------------------------------
// Kernel 1: fused QKV projection + partial channel-attention logits.
// grid (NN/128, B), block 256.
// Block computes stacked [192 rows x 128 n-cols] projection (q:0-63, k:64-127,
// v:128-191) with BK=32, thread microtile 12x8 (rows ty+16r, r=0..11).
// Then: v -> global, k -> smem, logits partial q·k^T over this block's 128
// columns via in-register q + shuffle reduction -> g_lp.
// ---------------------------------------------------------------------------
__global__ __launch_bounds__(256) void qkv_logits_kernel(
    const float* __restrict__ x,
    const float* __restrict__ wq, const float* __restrict__ bq,
    const float* __restrict__ wk, const float* __restrict__ bk,
    const float* __restrict__ wv, const float* __restrict__ bv)
{
    // 48 KB union:
    //   phase 1: Ws[32][193] (6176 f) | Xs[32][128] (4096 f)
    //   phase 2: Ks[64][128] (8192 f) | Ls[4096]
    __shared__ float smem[12288];
    float (*Ws)[193] = reinterpret_cast<float(*)[193]>(smem);
    float (*Xs)[128] = reinterpret_cast<float(*)[128]>(smem + 6176);
    float (*Ks)[128] = reinterpret_cast<float(*)[128]>(smem);
    float* Ls        = smem + 8192;

    const int b      = blockIdx.y;
    const int n_tile = blockIdx.x;
    const int n_base = n_tile * 128;
    const int tid = threadIdx.x;
    const int ty = tid >> 4, tx = tid & 15;
    const int n0 = tx * 8;

    const float* xb = x + (size_t)b * CC * NN;

    float acc[12][8];
    #pragma unroll
    for (int r = 0; r < 12; r++)
        #pragma unroll
        for (int j = 0; j < 8; j++) acc[r][j] = 0.f;

    for (int k0 = 0; k0 < CC; k0 += 32) {
        // Load stacked W chunk [192 m, 32 k] -> Ws[k][m]
        #pragma unroll
        for (int w = 0; w < 3; w++) {
            const float* W = (w == 0) ? wq : ((w == 1) ? wk : wv);
            #pragma unroll
            for (int i = 0; i < 8; i++) {
                int idx = i * 256 + tid;          // 0..2047
                int m = idx >> 5, kk = idx & 31;  // kk == tid&31 (coalesced)
                Ws[kk][w * 64 + m] = W[m * CC + k0 + kk];
            }
        }
        // Load x chunk [32 k, 128 n] -> Xs[k][n] (float4)
        const float4* xsrc = reinterpret_cast<const float4*>(xb + (size_t)k0 * NN + n_base);
        #pragma unroll
        for (int j = 0; j < 4; j++) {
            int idx4 = j * 256 + tid;             // 0..1023
            int k = idx4 >> 5, n4 = idx4 & 31;
            *reinterpret_cast<float4*>(&Xs[k][n4 * 4]) = xsrc[(size_t)k * (NN / 4) + n4];
        }
        __syncthreads();

        #pragma unroll
        for (int k = 0; k < 32; k++) {
            float a[12];
            #pragma unroll
            for (int r = 0; r < 12; r++) a[r] = Ws[k][ty + 16 * r];
            float4 v0 = *reinterpret_cast<const float4*>(&Xs[k][n0]);
            float4 v1 = *reinterpret_cast<const float4*>(&Xs[k][n0 + 4]);
            float xv[8] = {v0.x, v0.y, v0.z, v0.w, v1.x, v1.y, v1.z, v1.w};
            #pragma unroll
            for (int r = 0; r < 12; r++)
                #pragma unroll
                for (int j = 0; j < 8; j++)
                    acc[r][j] = fmaf(a[r], xv[j], acc[r][j]);
        }
        __syncthreads();
    }

    // Add biases
    #pragma unroll
    for (int r = 0; r < 4; r++) {
        float bqv = bq[ty + 16 * r];
        float bkv = bk[ty + 16 * r];
        float bvv = bv[ty + 16 * r];
        #pragma unroll
        for (int j = 0; j < 8; j++) {
            acc[r][j]     += bqv;   // q rows
            acc[r + 4][j] += bkv;   // k rows
            acc[r + 8][j] += bvv;   // v rows
        }
    }

    // Write v tile to global (rows r=8..11 -> v channel ty+16*(r-8))
    {
        float* vout = g_v + (size_t)b * CBOT * NN + n_base + n0;
        #pragma unroll
        for (int r = 8; r < 12; r++) {
            int vc = ty + 16 * (r - 8);
            float4 r0 = {acc[r][0], acc[r][1], acc[r][2], acc[r][3]};
            float4 r1 = {acc[r][4], acc[r][5], acc[r][6], acc[r][7]};
            float* orow = vout + (size_t)vc * NN;
            *reinterpret_cast<float4*>(orow)     = r0;
            *reinterpret_cast<float4*>(orow + 4) = r1;
        }
    }

    // Phase 2: k rows -> smem Ks[d][n]
    __syncthreads();   // everyone done reading Ws/Xs
    #pragma unroll
    for (int r = 4; r < 8; r++) {
        int kc = ty + 16 * (r - 4);
        float4 r0 = {acc[r][0], acc[r][1], acc[r][2], acc[r][3]};
        float4 r1 = {acc[r][4], acc[r][5], acc[r][6], acc[r][7]};
        *reinterpret_cast<float4*>(&Ks[kc][n0])     = r0;
        *reinterpret_cast<float4*>(&Ks[kc][n0 + 4]) = r1;
    }
    __syncthreads();

    // Partial logits: L[c][d] = sum over this block's 128 n of q[c,n]*k[d,n].
    // q rows (r=0..3, c=ty+16r) live in registers; reduce across tx lanes.
    for (int d = 0; d < CBOT; d++) {
        float4 k0v = *reinterpret_cast<const float4*>(&Ks[d][n0]);
        float4 k1v = *reinterpret_cast<const float4*>(&Ks[d][n0 + 4]);
        float kd[8] = {k0v.x, k0v.y, k0v.z, k0v.w, k1v.x, k1v.y, k1v.z, k1v.w};
        float part[4] = {0.f, 0.f, 0.f, 0.f};
        #pragma unroll
        for (int r = 0; r < 4; r++)
            #pragma unroll
            for (int j = 0; j < 8; j++)
                part[r] = fmaf(acc[r][j], kd[j], part[r]);
        // reduce over 16 tx lanes (xor bits 0..3 stay within half-warp)
        #pragma unroll
        for (int off = 1; off < 16; off <<= 1) {
            #pragma unroll
            for (int r = 0; r < 4; r++)
                part[r] += __shfl_xor_sync(0xffffffffu, part[r], off);
        }
        if (tx == 0) {
            #pragma unroll
            for (int r = 0; r < 4; r++)
                Ls[(ty + 16 * r) * CBOT + d] = part[r];
        }
    }
    __syncthreads();

    // Dump Ls -> g_lp (coalesced float4)
    {
        float4* dst = reinterpret_cast<float4*>(
            g_lp + (size_t)(b * NTILE + n_tile) * (CBOT * CBOT));
        const float4* src = reinterpret_cast<const float4*>(Ls);
        #pragma unroll
        for (int i = 0; i < 4; i++)
            dst[i * 256 + tid] = src[i * 256 + tid];
    }
}

// ---------------------------------------------------------------------------
// Kernel 2: reduce partials -> softmax(rows) -> M = gamma * (w_o @ attn).
// grid (B, 4), block 256.
// ---------------------------------------------------------------------------
__global__ __launch_bounds__(256) void softmax_m_kernel(
    const float* __restrict__ w_o, const float* __restrict__ gamma)
{
    __shared__ float L[CBOT * CBOT];  // 16 KB
    const int b = blockIdx.x;
    const int cbase = blockIdx.y * 128;
    const int tid = threadIdx.x;

    // Reduce NTILE partials
    #pragma unroll
    for (int t = 0; t < 16; t++) {
        int idx = tid + 256 * t;
        float s0 = 0.f;
        #pragma unroll 8
        for (int s = 0; s < NTILE; s++)
            s0 += g_lp[(size_t)(b * NTILE + s) * (CBOT * CBOT) + idx];
        L[idx] = s0;
    }
    __syncthreads();

    // Row softmax (64 rows, threads 0..63)
    if (tid < CBOT) {
        float* row = &L[tid * CBOT];
        float mx = row[0];
        #pragma unroll
        for (int d = 1; d < CBOT; d++) mx = fmaxf(mx, row[d]);
        float sum = 0.f;
        #pragma unroll
        for (int d = 0; d < CBOT; d++) { float e = expf(row[d] - mx); row[d] = e; sum += e; }
        float inv = 1.f / sum;
        #pragma unroll
        for (int d = 0; d < CBOT; d++) row[d] *= inv;
    }
    __syncthreads();

    // M[c][d] = gamma * sum_e w_o[c][e] * attn[e][d]   (128 c-rows per block)
    const float g = gamma[0];
    for (int o = tid; o < 128 * CBOT; o += 256) {
        int c = cbase + (o >> 6);
        int d = o & 63;
        float sum = 0.f;
        #pragma unroll
        for (int e = 0; e < CBOT; e++)
            sum = fmaf(w_o[c * CBOT + e], L[e * CBOT + d], sum);
        g_M[((size_t)b * CC + c) * CBOT + d] = g * sum;
    }
}

// ---------------------------------------------------------------------------
// Kernel 3: out = M @ v + gamma*b_o + x.
// grid (NN/128, CC/256, B), block 512.  Tile [256 c, 128 n], K=64 in two
// 32-chunks.  Thread microtile 8x8.  smem exactly 48 KB.
// ---------------------------------------------------------------------------
__global__ __launch_bounds__(512, 1) void out_kernel(
    const float* __restrict__ x,
    const float* __restrict__ b_o, const float* __restrict__ gamma,
    float* __restrict__ out)
{
    __shared__ float Msh[32][256];   // [k][c]  (a-reads are broadcast: conflict-free)
    __shared__ float Vs[32][128];    // [k][n]

    const int b = blockIdx.z;
    const int c_base = blockIdx.y * 256;
    const int n_base = blockIdx.x * 128;
    const int tid = threadIdx.x;
    const int ty = tid >> 4, tx = tid & 15;   // ty 0..31, tx 0..15
    const int c0 = ty * 8, n0 = tx * 8;

    const float* Mb = g_M + ((size_t)b * CC + c_base) * CBOT;
    const float* vb = g_v + (size_t)b * CBOT * NN;

    float acc[8][8];
    #pragma unroll
    for (int i = 0; i < 8; i++)
        #pragma unroll
        for (int j = 0; j < 8; j++) acc[i][j] = 0.f;

    for (int k0 = 0; k0 < CBOT; k0 += 32) {
        // M chunk [256 c, 32 k] -> Msh[k][c] (conflict-free smem stores)
        #pragma unroll
        for (int i = 0; i < 16; i++) {
            int idx = i * 512 + tid;          // 0..8191
            int c = idx & 255, k = idx >> 8;  // consecutive lanes -> consecutive c
            Msh[k][c] = Mb[(size_t)c * CBOT + k0 + k];
        }
        // v chunk [32 k, 128 n] -> Vs[k][n] (float4)
        const float4* vsrc = reinterpret_cast<const float4*>(vb + (size_t)k0 * NN + n_base);
        #pragma unroll
        for (int j = 0; j < 2; j++) {
            int idx4 = j * 512 + tid;         // 0..1023
            int k = idx4 >> 5, n4 = idx4 & 31;
            *reinterpret_cast<float4*>(&Vs[k][n4 * 4]) = vsrc[(size_t)k * (NN / 4) + n4];
        }
        __syncthreads();

        #pragma unroll
        for (int k = 0; k < 32; k++) {
            float4 a0 = *reinterpret_cast<const float4*>(&Msh[k][c0]);
            float4 a1 = *reinterpret_cast<const float4*>(&Msh[k][c0 + 4]);
            float a[8] = {a0.x, a0.y, a0.z, a0.w, a1.x, a1.y, a1.z, a1.w};
            float4 v0 = *reinterpret_cast<const float4*>(&Vs[k][n0]);
            float4 v1 = *reinterpret_cast<const float4*>(&Vs[k][n0 + 4]);
            float xv[8] = {v0.x, v0.y, v0.z, v0.w, v1.x, v1.y, v1.z, v1.w};
            #pragma unroll
            for (int i = 0; i < 8; i++)
                #pragma unroll
                for (int j = 0; j < 8; j++)
                    acc[i][j] = fmaf(a[i], xv[j], acc[i][j]);
        }
        __syncthreads();
    }

    // Epilogue: += gamma*b_o + residual x, float4 stores
    const float g = gamma[0];
    #pragma unroll
    for (int i = 0; i < 8; i++) {
        int c = c_base + c0 + i;
        float gb = g * b_o[c];
        const float* xr = x + ((size_t)b * CC + c) * NN + n_base + n0;
        float* orow = out + ((size_t)b * CC + c) * NN + n_base + n0;
        float4 x0 = *reinterpret_cast<const float4*>(xr);
        float4 x1 = *reinterpret_cast<const float4*>(xr + 4);
        float4 r0 = {acc[i][0] + gb + x0.x, acc[i][1] + gb + x0.y,
                     acc[i][2] + gb + x0.z, acc[i][3] + gb + x0.w};
        float4 r1 = {acc[i][4] + gb + x1.x, acc[i][5] + gb + x1.y,
                     acc[i][6] + gb + x1.z, acc[i][7] + gb + x1.w};
        *reinterpret_cast<float4*>(orow)     = r0;
        *reinterpret_cast<float4*>(orow + 4) = r1;
    }
}

// ---------------------------------------------------------------------------
// Launch
// ---------------------------------------------------------------------------
extern "C" void kernel_launch(void* const* d_in, const int* in_sizes, int n_in,
                              void* d_out, int out_size)
{
    const float* x     = (const float*)d_in[0];
    const float* w_q   = (const float*)d_in[1];
    const float* b_q   = (const float*)d_in[2];
    const float* w_k   = (const float*)d_in[3];
    const float* b_k   = (const float*)d_in[4];
    const float* w_v   = (const float*)d_in[5];
    const float* b_v   = (const float*)d_in[6];
    const float* w_o   = (const float*)d_in[7];
    const float* b_o   = (const float*)d_in[8];
    const float* gamma = (const float*)d_in[9];
    float* out = (float*)d_out;

    qkv_logits_kernel<<<dim3(NN / 128, BB), 256>>>(x, w_q, b_q, w_k, b_k, w_v, b_v);
    softmax_m_kernel<<<dim3(BB, 4), 256>>>(w_o, gamma);
    out_kernel<<<dim3(NN / 128, CC / 256, BB), 512>>>(x, b_o, gamma, out);
}

// round 3
// speedup vs baseline: 2.1057x; 2.1057x over previous
#include <cuda_runtime.h>
#include <cuda_bf16.h>
#include <math.h>
#include <stdint.h>

// Problem constants
#define BB 16
#define CC 512
#define CB 64
#define NN 4096
#define NT 32    // n-tiles of 128 per batch

// ---------------------------------------------------------------------------
// Scratch (static __device__ arrays — no runtime allocation)
// ---------------------------------------------------------------------------
__device__ __align__(16) __nv_bfloat16 g_v_hi[BB * CB * NN];   // 8 MB
__device__ __align__(16) __nv_bfloat16 g_v_lo[BB * CB * NN];   // 8 MB
__device__ float g_lp[BB * NT * CB * CB];                      // 8 MB
__device__ __align__(16) __nv_bfloat16 g_M_hi[BB * CC * CB];   // 1 MB
__device__ __align__(16) __nv_bfloat16 g_M_lo[BB * CC * CB];   // 1 MB

// ---------------------------------------------------------------------------
// MMA helpers (Ampere-style warp mma, bf16 in / fp32 accum)
// ---------------------------------------------------------------------------
__device__ __forceinline__ uint32_t sptr(const void* p) {
    return (uint32_t)__cvta_generic_to_shared(p);
}
__device__ __forceinline__ void ldm4(uint32_t* r, uint32_t a) {
    asm volatile("ldmatrix.sync.aligned.m8n8.x4.shared.b16 {%0,%1,%2,%3}, [%4];"
        : "=r"(r[0]), "=r"(r[1]), "=r"(r[2]), "=r"(r[3]) : "r"(a));
}
__device__ __forceinline__ void ldm4t(uint32_t* r, uint32_t a) {
    asm volatile("ldmatrix.sync.aligned.m8n8.x4.trans.shared.b16 {%0,%1,%2,%3}, [%4];"
        : "=r"(r[0]), "=r"(r[1]), "=r"(r[2]), "=r"(r[3]) : "r"(a));
}
__device__ __forceinline__ void mma16816(float* c, const uint32_t* a, const uint32_t* b) {
    asm volatile("mma.sync.aligned.m16n8k16.row.col.f32.bf16.bf16.f32 "
        "{%0,%1,%2,%3}, {%4,%5,%6,%7}, {%8,%9}, {%0,%1,%2,%3};"
        : "+f"(c[0]), "+f"(c[1]), "+f"(c[2]), "+f"(c[3])
        : "r"(a[0]), "r"(a[1]), "r"(a[2]), "r"(a[3]), "r"(b[0]), "r"(b[1]));
}
__device__ __forceinline__ void split2(float v, __nv_bfloat16& h, __nv_bfloat16& l) {
    h = __float2bfloat16_rn(v);
    l = __float2bfloat16_rn(v - __bfloat162float(h));
}

#define WS_STR 40     // W smem row stride (bf16 elems), conflict-free for ldmatrix
#define XS_STR 136    // X/V smem row stride
#define QS_STR 72     // Q/K smem row stride
#define MS_STR 40     // M smem row stride

// ---------------------------------------------------------------------------
// Kernel 1: fused QKV projection (bf16x3 mma) + logits partial (bf16x3 mma).
// grid (32, 16), block 256 (8 warps).
// Block tile: P[192 m x 128 n] = W[192,512] @ X[512,128(n-slice)].
// Warp grid 2(m) x 4(n): warp tile 96 x 32.  K-chunks of 32.
// Then q,k (fp32) re-split to bf16 hi/lo -> logits[64,64] partial via mma,
// contraction over this block's 128 n in two 64-halves (smem budget).
// v -> bf16 hi/lo planes in global.
// ---------------------------------------------------------------------------
__global__ __launch_bounds__(256, 1) void qkv_logits_kernel(
    const float* __restrict__ x,
    const float* __restrict__ wq, const float* __restrict__ bq,
    const float* __restrict__ wk, const float* __restrict__ bk,
    const float* __restrict__ wv, const float* __restrict__ bv)
{
    __shared__ __align__(16) __nv_bfloat16 smem[24064];  // 48128 B
    // phase 1 layout
    __nv_bfloat16* Whi = smem;            // [192][40] = 7680
    __nv_bfloat16* Wlo = smem + 7680;
    __nv_bfloat16* Xhi = smem + 15360;    // [32][136] = 4352
    __nv_bfloat16* Xlo = smem + 19712;    // end 24064
    // phase 2 layout (union; phase 1 data dead by then)
    __nv_bfloat16* Qhi = smem;            // [64][72] = 4608
    __nv_bfloat16* Qlo = smem + 4608;
    __nv_bfloat16* Khi = smem + 9216;
    __nv_bfloat16* Klo = smem + 13824;    // end 18432

    const int b = blockIdx.y, ntile = blockIdx.x;
    const int n_base = ntile * 128;
    const int tid = threadIdx.x, lane = tid & 31, wid = tid >> 5;
    const int wm = wid >> 2, wn = wid & 3;     // warp grid 2m x 4n
    const int g = lane >> 3, r = lane & 7;     // ldmatrix addressing
    const int q_r = lane >> 2, q_c = (lane & 3) * 2;  // C-fragment coords

    const float* xb = x + (size_t)b * CC * NN;

    float acc[6][4][4];
    #pragma unroll
    for (int i = 0; i < 6; i++)
        #pragma unroll
        for (int j = 0; j < 4; j++)
            #pragma unroll
            for (int e = 0; e < 4; e++) acc[i][j][e] = 0.f;

    for (int kc = 0; kc < 16; kc++) {
        const int k0 = kc * 32;
        // ---- load & split W chunk [192 m][32 k] ----
        #pragma unroll
        for (int i = 0; i < 6; i++) {
            int idx4 = i * 256 + tid;            // 0..1535
            int m = idx4 >> 3, kq = (idx4 & 7) * 4;
            const float* src;
            if (m < 64)       src = wq + m * CC;
            else if (m < 128) src = wk + (m - 64) * CC;
            else              src = wv + (m - 128) * CC;
            float4 v = *reinterpret_cast<const float4*>(src + k0 + kq);
            __nv_bfloat16 h0, l0, h1, l1, h2, l2, h3, l3;
            split2(v.x, h0, l0); split2(v.y, h1, l1);
            split2(v.z, h2, l2); split2(v.w, h3, l3);
            __nv_bfloat16* dh = Whi + m * WS_STR + kq;
            __nv_bfloat16* dl = Wlo + m * WS_STR + kq;
            *reinterpret_cast<__nv_bfloat162*>(dh)     = __nv_bfloat162(h0, h1);
            *reinterpret_cast<__nv_bfloat162*>(dh + 2) = __nv_bfloat162(h2, h3);
            *reinterpret_cast<__nv_bfloat162*>(dl)     = __nv_bfloat162(l0, l1);
            *reinterpret_cast<__nv_bfloat162*>(dl + 2) = __nv_bfloat162(l2, l3);
        }
        // ---- load & split X chunk [32 k][128 n] ----
        #pragma unroll
        for (int i = 0; i < 4; i++) {
            int idx4 = i * 256 + tid;            // 0..1023
            int k = idx4 >> 5, n4 = (idx4 & 31) * 4;
            float4 v = *reinterpret_cast<const float4*>(
                xb + (size_t)(k0 + k) * NN + n_base + n4);
            __nv_bfloat16 h0, l0, h1, l1, h2, l2, h3, l3;
            split2(v.x, h0, l0); split2(v.y, h1, l1);
            split2(v.z, h2, l2); split2(v.w, h3, l3);
            __nv_bfloat16* dh = Xhi + k * XS_STR + n4;
            __nv_bfloat16* dl = Xlo + k * XS_STR + n4;
            *reinterpret_cast<__nv_bfloat162*>(dh)     = __nv_bfloat162(h0, h1);
            *reinterpret_cast<__nv_bfloat162*>(dh + 2) = __nv_bfloat162(h2, h3);
            *reinterpret_cast<__nv_bfloat162*>(dl)     = __nv_bfloat162(l0, l1);
            *reinterpret_cast<__nv_bfloat162*>(dl + 2) = __nv_bfloat162(l2, l3);
        }
        __syncthreads();

        #pragma unroll
        for (int ks = 0; ks < 2; ks++) {
            const int kk = ks * 16;
            // B fragments (4 n-tiles of 8), hi & lo
            uint32_t Bh[4][2], Bl[4][2];
            #pragma unroll
            for (int nt2 = 0; nt2 < 2; nt2++) {
                int row = kk + (g & 1) * 8 + r;
                int col = wn * 32 + nt2 * 16 + (g >> 1) * 8;
                uint32_t t[4];
                ldm4t(t, sptr(Xhi + row * XS_STR + col));
                Bh[nt2*2][0]=t[0]; Bh[nt2*2][1]=t[1]; Bh[nt2*2+1][0]=t[2]; Bh[nt2*2+1][1]=t[3];
                ldm4t(t, sptr(Xlo + row * XS_STR + col));
                Bl[nt2*2][0]=t[0]; Bl[nt2*2][1]=t[1]; Bl[nt2*2+1][0]=t[2]; Bl[nt2*2+1][1]=t[3];
            }
            #pragma unroll
            for (int fm = 0; fm < 6; fm++) {
                int mrow = wm * 96 + fm * 16 + (g & 1) * 8 + r;
                int kcol = kk + (g >> 1) * 8;
                uint32_t Ah[4], Al[4];
                ldm4(Ah, sptr(Whi + mrow * WS_STR + kcol));
                ldm4(Al, sptr(Wlo + mrow * WS_STR + kcol));
                #pragma unroll
                for (int fn = 0; fn < 4; fn++) {
                    mma16816(acc[fm][fn], Ah, Bh[fn]);
                    mma16816(acc[fm][fn], Ah, Bl[fn]);
                    mma16816(acc[fm][fn], Al, Bh[fn]);
                }
            }
        }
        __syncthreads();
    }

    // ---- v rows (m 128..191, warp_m==1 frags 2..5): bias, split, -> global ----
    if (wm == 1) {
        #pragma unroll
        for (int fm = 2; fm < 6; fm++) {
            int cb0 = (fm - 2) * 16 + q_r;       // v channel of c0,c1
            float bv0 = bv[cb0], bv8 = bv[cb0 + 8];
            #pragma unroll
            for (int fn = 0; fn < 4; fn++) {
                int n = n_base + wn * 32 + fn * 8 + q_c;
                float v0 = acc[fm][fn][0] + bv0, v1 = acc[fm][fn][1] + bv0;
                float v2 = acc[fm][fn][2] + bv8, v3 = acc[fm][fn][3] + bv8;
                __nv_bfloat16 h0, l0, h1, l1, h2, l2, h3, l3;
                split2(v0, h0, l0); split2(v1, h1, l1);
                split2(v2, h2, l2); split2(v3, h3, l3);
                size_t o0 = ((size_t)b * CB + cb0) * NN + n;
                size_t o8 = o0 + (size_t)8 * NN;
                *reinterpret_cast<__nv_bfloat162*>(g_v_hi + o0) = __nv_bfloat162(h0, h1);
                *reinterpret_cast<__nv_bfloat162*>(g_v_lo + o0) = __nv_bfloat162(l0, l1);
                *reinterpret_cast<__nv_bfloat162*>(g_v_hi + o8) = __nv_bfloat162(h2, h3);
                *reinterpret_cast<__nv_bfloat162*>(g_v_lo + o8) = __nv_bfloat162(l2, l3);
            }
        }
    }

    // ---- logits: two n-halves; q,k re-split to bf16 hi/lo, mma accumulate ----
    float lacc[4][4];
    #pragma unroll
    for (int i = 0; i < 4; i++)
        #pragma unroll
        for (int j = 0; j < 4; j++) lacc[i][j] = 0.f;
    const int wml = wid >> 1, wnl = wid & 1;     // logits warp grid 4m x 2n

    #pragma unroll
    for (int p = 0; p < 2; p++) {
        __syncthreads();   // prior smem consumers done
        if ((wn >> 1) == p) {   // this warp's n-slice belongs to half p
            #pragma unroll
            for (int fm = 0; fm < 6; fm++) {
                int m0 = wm * 96 + fm * 16 + q_r;
                if (m0 < 128) {   // q or k rows (frags never straddle boundaries)
                    bool isq = (m0 < 64);
                    int r0 = isq ? m0 : (m0 - 64);
                    float bb0 = isq ? bq[m0] : bk[m0 - 64];
                    float bb8 = isq ? bq[m0 + 8] : bk[m0 - 56];
                    __nv_bfloat16* Phi = isq ? Qhi : Khi;
                    __nv_bfloat16* Plo = isq ? Qlo : Klo;
                    #pragma unroll
                    for (int fn = 0; fn < 4; fn++) {
                        int col = wn * 32 + fn * 8 + q_c - p * 64;
                        float v0 = acc[fm][fn][0] + bb0, v1 = acc[fm][fn][1] + bb0;
                        float v2 = acc[fm][fn][2] + bb8, v3 = acc[fm][fn][3] + bb8;
                        __nv_bfloat16 h0, l0, h1, l1, h2, l2, h3, l3;
                        split2(v0, h0, l0); split2(v1, h1, l1);
                        split2(v2, h2, l2); split2(v3, h3, l3);
                        *reinterpret_cast<__nv_bfloat162*>(Phi + r0 * QS_STR + col)       = __nv_bfloat162(h0, h1);
                        *reinterpret_cast<__nv_bfloat162*>(Plo + r0 * QS_STR + col)       = __nv_bfloat162(l0, l1);
                        *reinterpret_cast<__nv_bfloat162*>(Phi + (r0 + 8) * QS_STR + col) = __nv_bfloat162(h2, h3);
                        *reinterpret_cast<__nv_bfloat162*>(Plo + (r0 + 8) * QS_STR + col) = __nv_bfloat162(l2, l3);
                    }
                }
            }
        }
        __syncthreads();
        // logits mma over this 64-wide half (4 k16 steps)
        #pragma unroll
        for (int ks = 0; ks < 4; ks++) {
            const int kk = ks * 16;
            uint32_t Ah[4], Al[4];
            {
                int row = wml * 16 + (g & 1) * 8 + r;
                int col = kk + (g >> 1) * 8;
                ldm4(Ah, sptr(Qhi + row * QS_STR + col));
                ldm4(Al, sptr(Qlo + row * QS_STR + col));
            }
            #pragma unroll
            for (int dt = 0; dt < 2; dt++) {
                // B (col-major natural): non-trans x4 on K_sm[d][n]
                int drow = wnl * 32 + dt * 16 + (g >> 1) * 8 + r;
                int dcol = kk + (g & 1) * 8;
                uint32_t Bh_[4], Bl_[4];
                ldm4(Bh_, sptr(Khi + drow * QS_STR + dcol));
                ldm4(Bl_, sptr(Klo + drow * QS_STR + dcol));
                mma16816(lacc[dt*2],     Ah, Bh_ + 0);
                mma16816(lacc[dt*2],     Ah, Bl_ + 0);
                mma16816(lacc[dt*2],     Al, Bh_ + 0);
                mma16816(lacc[dt*2 + 1], Ah, Bh_ + 2);
                mma16816(lacc[dt*2 + 1], Ah, Bl_ + 2);
                mma16816(lacc[dt*2 + 1], Al, Bh_ + 2);
            }
        }
    }

    // ---- write logits partial [64,64] ----
    float* lp = g_lp + (size_t)(b * NT + ntile) * (CB * CB);
    #pragma unroll
    for (int df = 0; df < 4; df++) {
        int cr = wml * 16 + q_r;
        int dc = wnl * 32 + df * 8 + q_c;
        lp[cr * CB + dc]           = lacc[df][0];
        lp[cr * CB + dc + 1]       = lacc[df][1];
        lp[(cr + 8) * CB + dc]     = lacc[df][2];
        lp[(cr + 8) * CB + dc + 1] = lacc[df][3];
    }
}

// ---------------------------------------------------------------------------
// Kernel 2: reduce partials -> softmax -> M = gamma*(w_o@attn) -> bf16 hi/lo.
// grid (16, 4), block 256.
// ---------------------------------------------------------------------------
__global__ __launch_bounds__(256) void softmax_m_kernel(
    const float* __restrict__ w_o, const float* __restrict__ gamma)
{
    __shared__ float L[CB * CB];
    const int b = blockIdx.x, cbase = blockIdx.y * 128, tid = threadIdx.x;

    #pragma unroll
    for (int t = 0; t < 16; t++) {
        int idx = tid + 256 * t;
        float s0 = 0.f;
        #pragma unroll 8
        for (int s = 0; s < NT; s++)
            s0 += g_lp[(size_t)(b * NT + s) * (CB * CB) + idx];
        L[idx] = s0;
    }
    __syncthreads();

    if (tid < CB) {
        float* row = &L[tid * CB];
        float mx = row[0];
        #pragma unroll
        for (int d = 1; d < CB; d++) mx = fmaxf(mx, row[d]);
        float sum = 0.f;
        #pragma unroll
        for (int d = 0; d < CB; d++) { float e = expf(row[d] - mx); row[d] = e; sum += e; }
        float inv = 1.f / sum;
        #pragma unroll
        for (int d = 0; d < CB; d++) row[d] *= inv;
    }
    __syncthreads();

    const float gm = gamma[0];
    for (int o = tid; o < 128 * CB; o += 256) {
        int c = cbase + (o >> 6), d = o & 63;
        float sum = 0.f;
        #pragma unroll
        for (int e = 0; e < CB; e++)
            sum = fmaf(w_o[c * CB + e], L[e * CB + d], sum);
        float mval = gm * sum;
        __nv_bfloat16 h, l;
        split2(mval, h, l);
        size_t off = ((size_t)b * CC + c) * CB + d;
        g_M_hi[off] = h;
        g_M_lo[off] = l;
    }
}

// ---------------------------------------------------------------------------
// Kernel 3: out = M@v (bf16x3 mma) + gamma*b_o + x.
// grid (32, 4, 16), block 256.  Block tile [128 c x 128 n], K=64 in 2 chunks.
// Warp grid 4(m) x 2(n): warp tile 32 x 64.
// ---------------------------------------------------------------------------
__global__ __launch_bounds__(256, 1) void out_kernel(
    const float* __restrict__ x,
    const float* __restrict__ b_o, const float* __restrict__ gamma,
    float* __restrict__ out)
{
    __shared__ __align__(16) __nv_bfloat16 smem[18944];  // 37888 B
    __nv_bfloat16* Mhi = smem;            // [128][40] = 5120
    __nv_bfloat16* Mlo = smem + 5120;
    __nv_bfloat16* Vhi = smem + 10240;    // [32][136] = 4352
    __nv_bfloat16* Vlo = smem + 14592;

    const int b = blockIdx.z, cb0 = blockIdx.y * 128, n_base = blockIdx.x * 128;
    const int tid = threadIdx.x, lane = tid & 31, wid = tid >> 5;
    const int wm = wid >> 1, wn = wid & 1;
    const int g = lane >> 3, r = lane & 7;
    const int q_r = lane >> 2, q_c = (lane & 3) * 2;

    float acc[2][8][4];
    #pragma unroll
    for (int i = 0; i < 2; i++)
        #pragma unroll
        for (int j = 0; j < 8; j++)
            #pragma unroll
            for (int e = 0; e < 4; e++) acc[i][j][e] = 0.f;

    #pragma unroll
    for (int ec = 0; ec < 2; ec++) {
        const int e0 = ec * 32;
        // M planes [128 c][32 e]
        #pragma unroll
        for (int i = 0; i < 8; i++) {
            int idx = i * 256 + tid;
            int c = idx >> 4, e2 = (idx & 15) * 2;
            size_t off = ((size_t)b * CC + cb0 + c) * CB + e0 + e2;
            *reinterpret_cast<__nv_bfloat162*>(Mhi + c * MS_STR + e2) =
                *reinterpret_cast<const __nv_bfloat162*>(g_M_hi + off);
            *reinterpret_cast<__nv_bfloat162*>(Mlo + c * MS_STR + e2) =
                *reinterpret_cast<const __nv_bfloat162*>(g_M_lo + off);
        }
        // V planes [32 e][128 n]
        #pragma unroll
        for (int i = 0; i < 4; i++) {
            int idx = i * 256 + tid;
            int e = idx >> 5, n4 = (idx & 31) * 4;
            size_t off = ((size_t)b * CB + e0 + e) * NN + n_base + n4;
            *reinterpret_cast<uint2*>(Vhi + e * XS_STR + n4) =
                *reinterpret_cast<const uint2*>(g_v_hi + off);
            *reinterpret_cast<uint2*>(Vlo + e * XS_STR + n4) =
                *reinterpret_cast<const uint2*>(g_v_lo + off);
        }
        __syncthreads();

        #pragma unroll
        for (int ks = 0; ks < 2; ks++) {
            const int kk = ks * 16;
            uint32_t Bh[8][2], Bl[8][2];
            #pragma unroll
            for (int nt = 0; nt < 4; nt++) {
                int row = kk + (g & 1) * 8 + r;
                int col = wn * 64 + nt * 16 + (g >> 1) * 8;
                uint32_t t[4];
                ldm4t(t, sptr(Vhi + row * XS_STR + col));
                Bh[nt*2][0]=t[0]; Bh[nt*2][1]=t[1]; Bh[nt*2+1][0]=t[2]; Bh[nt*2+1][1]=t[3];
                ldm4t(t, sptr(Vlo + row * XS_STR + col));
                Bl[nt*2][0]=t[0]; Bl[nt*2][1]=t[1]; Bl[nt*2+1][0]=t[2]; Bl[nt*2+1][1]=t[3];
            }
            #pragma unroll
            for (int fm = 0; fm < 2; fm++) {
                int mrow = wm * 32 + fm * 16 + (g & 1) * 8 + r;
                int kcol = kk + (g >> 1) * 8;
                uint32_t Ah[4], Al[4];
                ldm4(Ah, sptr(Mhi + mrow * MS_STR + kcol));
                ldm4(Al, sptr(Mlo + mrow * MS_STR + kcol));
                #pragma unroll
                for (int fn = 0; fn < 8; fn++) {
                    mma16816(acc[fm][fn], Ah, Bh[fn]);
                    mma16816(acc[fm][fn], Ah, Bl[fn]);
                    mma16816(acc[fm][fn], Al, Bh[fn]);
                }
            }
        }
        __syncthreads();
    }

    // Epilogue: += gamma*b_o + residual x
    const float gm = gamma[0];
    #pragma unroll
    for (int fm = 0; fm < 2; fm++) {
        int c0 = cb0 + wm * 32 + fm * 16 + q_r;
        float gb0 = gm * b_o[c0], gb8 = gm * b_o[c0 + 8];
        #pragma unroll
        for (int fn = 0; fn < 8; fn++) {
            int n = n_base + wn * 64 + fn * 8 + q_c;
            size_t o0 = ((size_t)b * CC + c0) * NN + n;
            size_t o8 = o0 + (size_t)8 * NN;
            float2 x0 = *reinterpret_cast<const float2*>(x + o0);
            float2 x8 = *reinterpret_cast<const float2*>(x + o8);
            float2 r0 = {acc[fm][fn][0] + gb0 + x0.x, acc[fm][fn][1] + gb0 + x0.y};
            float2 r8 = {acc[fm][fn][2] + gb8 + x8.x, acc[fm][fn][3] + gb8 + x8.y};
            *reinterpret_cast<float2*>(out + o0) = r0;
            *reinterpret_cast<float2*>(out + o8) = r8;
        }
    }
}

// ---------------------------------------------------------------------------
// Launch
// ---------------------------------------------------------------------------
extern "C" void kernel_launch(void* const* d_in, const int* in_sizes, int n_in,
                              void* d_out, int out_size)
{
    const float* x     = (const float*)d_in[0];
    const float* w_q   = (const float*)d_in[1];
    const float* b_q   = (const float*)d_in[2];
    const float* w_k   = (const float*)d_in[3];
    const float* b_k   = (const float*)d_in[4];
    const float* w_v   = (const float*)d_in[5];
    const float* b_v   = (const float*)d_in[6];
    const float* w_o   = (const float*)d_in[7];
    const float* b_o   = (const float*)d_in[8];
    const float* gamma = (const float*)d_in[9];
    float* out = (float*)d_out;

    qkv_logits_kernel<<<dim3(NT, BB), 256>>>(x, w_q, b_q, w_k, b_k, w_v, b_v);
    softmax_m_kernel<<<dim3(BB, 4), 256>>>(w_o, gamma);
    out_kernel<<<dim3(NN / 128, CC / 128, BB), 256>>>(x, b_o, gamma, out);
}

// round 5
// speedup vs baseline: 2.1446x; 1.0185x over previous
#include <cuda_runtime.h>
#include <cuda_bf16.h>
#include <math.h>
#include <stdint.h>

// Problem constants
#define BB 16
#define CC 512
#define CB 64
#define NN 4096
#define NT 32    // n-tiles of 128 per batch

// ---------------------------------------------------------------------------
// Scratch (static __device__ arrays — no runtime allocation)
// ---------------------------------------------------------------------------
__device__ __align__(16) __nv_bfloat16 g_v_hi[BB * CB * NN];   // 8 MB
__device__ __align__(16) __nv_bfloat16 g_v_lo[BB * CB * NN];   // 8 MB
__device__ float g_lp[BB * NT * CB * CB];                      // 8 MB
__device__ __align__(16) __nv_bfloat16 g_M_hi[BB * CC * CB];   // 1 MB
__device__ __align__(16) __nv_bfloat16 g_M_lo[BB * CC * CB];   // 1 MB
// Pre-split stacked QKV weights, chunk-major: [16 kc][192 m][32 k]
__device__ __align__(16) __nv_bfloat16 g_w_hi[16 * 192 * 32];
__device__ __align__(16) __nv_bfloat16 g_w_lo[16 * 192 * 32];

// ---------------------------------------------------------------------------
// MMA helpers (warp mma, bf16 in / fp32 accum)
// ---------------------------------------------------------------------------
__device__ __forceinline__ uint32_t sptr(const void* p) {
    return (uint32_t)__cvta_generic_to_shared(p);
}
__device__ __forceinline__ void ldm4(uint32_t* r, uint32_t a) {
    asm volatile("ldmatrix.sync.aligned.m8n8.x4.shared.b16 {%0,%1,%2,%3}, [%4];"
        : "=r"(r[0]), "=r"(r[1]), "=r"(r[2]), "=r"(r[3]) : "r"(a));
}
__device__ __forceinline__ void ldm4t(uint32_t* r, uint32_t a) {
    asm volatile("ldmatrix.sync.aligned.m8n8.x4.trans.shared.b16 {%0,%1,%2,%3}, [%4];"
        : "=r"(r[0]), "=r"(r[1]), "=r"(r[2]), "=r"(r[3]) : "r"(a));
}
__device__ __forceinline__ void mma16816(float* c, const uint32_t* a, const uint32_t* b) {
    asm volatile("mma.sync.aligned.m16n8k16.row.col.f32.bf16.bf16.f32 "
        "{%0,%1,%2,%3}, {%4,%5,%6,%7}, {%8,%9}, {%0,%1,%2,%3};"
        : "+f"(c[0]), "+f"(c[1]), "+f"(c[2]), "+f"(c[3])
        : "r"(a[0]), "r"(a[1]), "r"(a[2]), "r"(a[3]), "r"(b[0]), "r"(b[1]));
}
__device__ __forceinline__ void split2(float v, __nv_bfloat16& h, __nv_bfloat16& l) {
    h = __float2bfloat16_rn(v);
    l = __float2bfloat16_rn(v - __bfloat162float(h));
}

#define WS 40     // W smem row stride (bf16)
#define XS 136    // X/V smem row stride
#define QS 72     // Q/K smem row stride
#define MS 40     // M smem row stride

// ---------------------------------------------------------------------------
// Kernel 0: pre-split stacked W into bf16 hi/lo planes, chunk-major layout.
// grid 192, block 512.
// ---------------------------------------------------------------------------
__global__ __launch_bounds__(512) void prep_w_kernel(
    const float* __restrict__ wq, const float* __restrict__ wk,
    const float* __restrict__ wv)
{
    const int m = blockIdx.x, t = threadIdx.x;
    const float* src = (m < 64) ? (wq + m * CC)
                     : (m < 128) ? (wk + (m - 64) * CC)
                                 : (wv + (m - 128) * CC);
    float v = src[t];
    __nv_bfloat16 h, l;
    split2(v, h, l);
    int dst = (t >> 5) * (192 * 32) + m * 32 + (t & 31);
    g_w_hi[dst] = h;
    g_w_lo[dst] = l;
}

// ---------------------------------------------------------------------------
// Kernel 1: fused QKV projection (bf16x3 mma) + logits partial (bf16x3 mma).
// grid (32, 16), block 512 (16 warps).
// Block tile P[192 m x 128 n]; warp grid 4m x 4n -> warp tile 48 x 32.
// ---------------------------------------------------------------------------
__global__ __launch_bounds__(512, 1) void qkv_logits_kernel(
    const float* __restrict__ x,
    const float* __restrict__ bq, const float* __restrict__ bk,
    const float* __restrict__ bv)
{
    __shared__ __align__(16) __nv_bfloat16 smem[24064];  // 48128 B
    __nv_bfloat16* Whi = smem;            // [192][40]
    __nv_bfloat16* Wlo = smem + 7680;
    __nv_bfloat16* Xhi = smem + 15360;    // [32][136]
    __nv_bfloat16* Xlo = smem + 19712;
    __nv_bfloat16* Qhi = smem;            // phase 2 union: [64][72] x4
    __nv_bfloat16* Qlo = smem + 4608;
    __nv_bfloat16* Khi = smem + 9216;
    __nv_bfloat16* Klo = smem + 13824;

    const int b = blockIdx.y, ntile = blockIdx.x;
    const int n_base = ntile * 128;
    const int tid = threadIdx.x, lane = tid & 31, wid = tid >> 5;
    const int wm = wid >> 2, wn = wid & 3;
    const int g = lane >> 3, r = lane & 7;
    const int q_r = lane >> 2, q_c = (lane & 3) * 2;

    const float* xb = x + (size_t)b * CC * NN;

    float acc[3][4][4];
    #pragma unroll
    for (int i = 0; i < 3; i++)
        #pragma unroll
        for (int j = 0; j < 4; j++)
            #pragma unroll
            for (int e = 0; e < 4; e++) acc[i][j][e] = 0.f;

    // precomputed ldmatrix byte addresses (offsets added in-loop are constants)
    const uint32_t uWa = sptr(Whi + (wm * 48 + (g & 1) * 8 + r) * WS + (g >> 1) * 8);
    const uint32_t uXb = sptr(Xhi + ((g & 1) * 8 + r) * XS + wn * 32 + (g >> 1) * 8);

    for (int kc = 0; kc < 16; kc++) {
        // ---- copy pre-split W chunk [192][32] (pure bf16 copies) ----
        {
            const uint2* sh = reinterpret_cast<const uint2*>(g_w_hi + kc * (192 * 32));
            const uint2* sl = reinterpret_cast<const uint2*>(g_w_lo + kc * (192 * 32));
            #pragma unroll
            for (int i = 0; i < 3; i++) {
                int idx = i * 512 + tid;          // 0..1535 uint2s
                int m = idx >> 3, k4 = (idx & 7) * 4;
                *reinterpret_cast<uint2*>(Whi + m * WS + k4) = sh[idx];
                *reinterpret_cast<uint2*>(Wlo + m * WS + k4) = sl[idx];
            }
        }
        // ---- load & split X chunk [32 k][128 n] ----
        {
            const int k0 = kc * 32;
            #pragma unroll
            for (int i = 0; i < 2; i++) {
                int idx = i * 512 + tid;          // 0..1023 float4s
                int k = idx >> 5, n4 = (idx & 31) * 4;
                float4 v = *reinterpret_cast<const float4*>(
                    xb + (size_t)(k0 + k) * NN + n_base + n4);
                __nv_bfloat16 h0, l0, h1, l1, h2, l2, h3, l3;
                split2(v.x, h0, l0); split2(v.y, h1, l1);
                split2(v.z, h2, l2); split2(v.w, h3, l3);
                __nv_bfloat16* dh = Xhi + k * XS + n4;
                __nv_bfloat16* dl = Xlo + k * XS + n4;
                *reinterpret_cast<__nv_bfloat162*>(dh)     = __nv_bfloat162(h0, h1);
                *reinterpret_cast<__nv_bfloat162*>(dh + 2) = __nv_bfloat162(h2, h3);
                *reinterpret_cast<__nv_bfloat162*>(dl)     = __nv_bfloat162(l0, l1);
                *reinterpret_cast<__nv_bfloat162*>(dl + 2) = __nv_bfloat162(l2, l3);
            }
        }
        __syncthreads();

        #pragma unroll
        for (int ks = 0; ks < 2; ks++) {
            uint32_t Bh[4][2], Bl[4][2];
            #pragma unroll
            for (int nt2 = 0; nt2 < 2; nt2++) {
                uint32_t t[4];
                ldm4t(t, uXb + ks * 4352 + nt2 * 32);
                Bh[nt2*2][0]=t[0]; Bh[nt2*2][1]=t[1]; Bh[nt2*2+1][0]=t[2]; Bh[nt2*2+1][1]=t[3];
                ldm4t(t, uXb + 8704 + ks * 4352 + nt2 * 32);
                Bl[nt2*2][0]=t[0]; Bl[nt2*2][1]=t[1]; Bl[nt2*2+1][0]=t[2]; Bl[nt2*2+1][1]=t[3];
            }
            #pragma unroll
            for (int fm = 0; fm < 3; fm++) {
                uint32_t Ah[4], Al[4];
                ldm4(Ah, uWa + fm * 1280 + ks * 32);
                ldm4(Al, uWa + 15360 + fm * 1280 + ks * 32);
                #pragma unroll
                for (int fn = 0; fn < 4; fn++) {
                    mma16816(acc[fm][fn], Ah, Bh[fn]);
                    mma16816(acc[fm][fn], Ah, Bl[fn]);
                    mma16816(acc[fm][fn], Al, Bh[fn]);
                }
            }
        }
        __syncthreads();
    }

    // ---- v rows (m >= 128): bias, split, -> global planes ----
    #pragma unroll
    for (int fm = 0; fm < 3; fm++) {
        int m0 = wm * 48 + fm * 16;
        if (m0 >= 128) {
            int c0 = m0 - 128 + q_r;
            float bv0 = bv[c0], bv8 = bv[c0 + 8];
            #pragma unroll
            for (int fn = 0; fn < 4; fn++) {
                int n = n_base + wn * 32 + fn * 8 + q_c;
                float v0 = acc[fm][fn][0] + bv0, v1 = acc[fm][fn][1] + bv0;
                float v2 = acc[fm][fn][2] + bv8, v3 = acc[fm][fn][3] + bv8;
                __nv_bfloat16 h0, l0, h1, l1, h2, l2, h3, l3;
                split2(v0, h0, l0); split2(v1, h1, l1);
                split2(v2, h2, l2); split2(v3, h3, l3);
                size_t o0 = ((size_t)b * CB + c0) * NN + n;
                size_t o8 = o0 + (size_t)8 * NN;
                *reinterpret_cast<__nv_bfloat162*>(g_v_hi + o0) = __nv_bfloat162(h0, h1);
                *reinterpret_cast<__nv_bfloat162*>(g_v_lo + o0) = __nv_bfloat162(l0, l1);
                *reinterpret_cast<__nv_bfloat162*>(g_v_hi + o8) = __nv_bfloat162(h2, h3);
                *reinterpret_cast<__nv_bfloat162*>(g_v_lo + o8) = __nv_bfloat162(l2, l3);
            }
        }
    }

    // ---- logits over two 64-n halves; q,k re-split -> bf16x3 mma ----
    float lacc[2][4];
    #pragma unroll
    for (int i = 0; i < 2; i++)
        #pragma unroll
        for (int j = 0; j < 4; j++) lacc[i][j] = 0.f;

    #pragma unroll
    for (int p = 0; p < 2; p++) {
        __syncthreads();
        if ((wn >> 1) == p) {
            #pragma unroll
            for (int fm = 0; fm < 3; fm++) {
                int m0f = wm * 48 + fm * 16;
                if (m0f < 128) {
                    int m0 = m0f + q_r;
                    bool isq = (m0f < 64);
                    int r0 = isq ? m0 : (m0 - 64);
                    float bb0 = isq ? bq[m0] : bk[m0 - 64];
                    float bb8 = isq ? bq[m0 + 8] : bk[m0 - 56];
                    __nv_bfloat16* Phi = isq ? Qhi : Khi;
                    __nv_bfloat16* Plo = isq ? Qlo : Klo;
                    #pragma unroll
                    for (int fn = 0; fn < 4; fn++) {
                        int col = wn * 32 + fn * 8 + q_c - p * 64;
                        float v0 = acc[fm][fn][0] + bb0, v1 = acc[fm][fn][1] + bb0;
                        float v2 = acc[fm][fn][2] + bb8, v3 = acc[fm][fn][3] + bb8;
                        __nv_bfloat16 h0, l0, h1, l1, h2, l2, h3, l3;
                        split2(v0, h0, l0); split2(v1, h1, l1);
                        split2(v2, h2, l2); split2(v3, h3, l3);
                        *reinterpret_cast<__nv_bfloat162*>(Phi + r0 * QS + col)       = __nv_bfloat162(h0, h1);
                        *reinterpret_cast<__nv_bfloat162*>(Plo + r0 * QS + col)       = __nv_bfloat162(l0, l1);
                        *reinterpret_cast<__nv_bfloat162*>(Phi + (r0 + 8) * QS + col) = __nv_bfloat162(h2, h3);
                        *reinterpret_cast<__nv_bfloat162*>(Plo + (r0 + 8) * QS + col) = __nv_bfloat162(l2, l3);
                    }
                }
            }
        }
        __syncthreads();
        #pragma unroll
        for (int ks = 0; ks < 4; ks++) {
            const int kk = ks * 16;
            uint32_t Ah[4], Al[4];
            {
                int row = wm * 16 + (g & 1) * 8 + r;
                int col = kk + (g >> 1) * 8;
                ldm4(Ah, sptr(Qhi + row * QS + col));
                ldm4(Al, sptr(Qlo + row * QS + col));
            }
            uint32_t Bh_[4], Bl_[4];
            {
                int drow = wn * 16 + (g >> 1) * 8 + r;
                int dcol = kk + (g & 1) * 8;
                ldm4(Bh_, sptr(Khi + drow * QS + dcol));
                ldm4(Bl_, sptr(Klo + drow * QS + dcol));
            }
            mma16816(lacc[0], Ah, Bh_ + 0);
            mma16816(lacc[0], Ah, Bl_ + 0);
            mma16816(lacc[0], Al, Bh_ + 0);
            mma16816(lacc[1], Ah, Bh_ + 2);
            mma16816(lacc[1], Ah, Bl_ + 2);
            mma16816(lacc[1], Al, Bh_ + 2);
        }
    }

    // ---- write logits partial [64,64] ----
    float* lp = g_lp + (size_t)(b * NT + ntile) * (CB * CB);
    #pragma unroll
    for (int df = 0; df < 2; df++) {
        int cr = wm * 16 + q_r;
        int dc = wn * 16 + df * 8 + q_c;
        lp[cr * CB + dc]           = lacc[df][0];
        lp[cr * CB + dc + 1]       = lacc[df][1];
        lp[(cr + 8) * CB + dc]     = lacc[df][2];
        lp[(cr + 8) * CB + dc + 1] = lacc[df][3];
    }
}

// ---------------------------------------------------------------------------
// Kernel 2: reduce partials -> softmax -> M = gamma*(w_o@attn) -> bf16 hi/lo.
// grid (16, 4), block 256.
// ---------------------------------------------------------------------------
__global__ __launch_bounds__(256) void softmax_m_kernel(
    const float* __restrict__ w_o, const float* __restrict__ gamma)
{
    __shared__ float L[CB * CB];
    const int b = blockIdx.x, cbase = blockIdx.y * 128, tid = threadIdx.x;

    #pragma unroll
    for (int t = 0; t < 16; t++) {
        int idx = tid + 256 * t;
        float s0 = 0.f;
        #pragma unroll 8
        for (int s = 0; s < NT; s++)
            s0 += g_lp[(size_t)(b * NT + s) * (CB * CB) + idx];
        L[idx] = s0;
    }
    __syncthreads();

    if (tid < CB) {
        float* row = &L[tid * CB];
        float mx = row[0];
        #pragma unroll
        for (int d = 1; d < CB; d++) mx = fmaxf(mx, row[d]);
        float sum = 0.f;
        #pragma unroll
        for (int d = 0; d < CB; d++) { float e = expf(row[d] - mx); row[d] = e; sum += e; }
        float inv = 1.f / sum;
        #pragma unroll
        for (int d = 0; d < CB; d++) row[d] *= inv;
    }
    __syncthreads();

    const float gm = gamma[0];
    for (int o = tid; o < 128 * CB; o += 256) {
        int c = cbase + (o >> 6), d = o & 63;
        float sum = 0.f;
        #pragma unroll
        for (int e = 0; e < CB; e++)
            sum = fmaf(w_o[c * CB + e], L[e * CB + d], sum);
        float mval = gm * sum;
        __nv_bfloat16 h, l;
        split2(mval, h, l);
        size_t off = ((size_t)b * CC + c) * CB + d;
        g_M_hi[off] = h;
        g_M_lo[off] = l;
    }
}

// ---------------------------------------------------------------------------
// Kernel 3: out = M@v (bf16x3 mma) + gamma*b_o + x.
// grid (32, 4, 16), block 256 (target 2 CTAs/SM).  Block tile [128c x 128n].
// Warp grid 4m x 2n: warp tile 32 x 64.  Smem-staged coalesced epilogue.
// ---------------------------------------------------------------------------
__global__ __launch_bounds__(256, 2) void out_kernel(
    const float* __restrict__ x,
    const float* __restrict__ b_o, const float* __restrict__ gamma,
    float* __restrict__ out)
{
    __shared__ __align__(16) __nv_bfloat16 smem[18944];  // 37888 B
    __nv_bfloat16* Mhi = smem;            // [128][40]
    __nv_bfloat16* Mlo = smem + 5120;
    __nv_bfloat16* Vhi = smem + 10240;    // [32][136]
    __nv_bfloat16* Vlo = smem + 14592;

    const int b = blockIdx.z, cb0 = blockIdx.y * 128, n_base = blockIdx.x * 128;
    const int tid = threadIdx.x, lane = tid & 31, wid = tid >> 5;
    const int wm = wid >> 1, wn = wid & 1;
    const int g = lane >> 3, r = lane & 7;
    const int q_r = lane >> 2, q_c = (lane & 3) * 2;

    float acc[2][8][4];
    #pragma unroll
    for (int i = 0; i < 2; i++)
        #pragma unroll
        for (int j = 0; j < 8; j++)
            #pragma unroll
            for (int e = 0; e < 4; e++) acc[i][j][e] = 0.f;

    #pragma unroll
    for (int ec = 0; ec < 2; ec++) {
        const int e0 = ec * 32;
        #pragma unroll
        for (int i = 0; i < 8; i++) {
            int idx = i * 256 + tid;
            int c = idx >> 4, e2 = (idx & 15) * 2;
            size_t off = ((size_t)b * CC + cb0 + c) * CB + e0 + e2;
            *reinterpret_cast<__nv_bfloat162*>(Mhi + c * MS + e2) =
                *reinterpret_cast<const __nv_bfloat162*>(g_M_hi + off);
            *reinterpret_cast<__nv_bfloat162*>(Mlo + c * MS + e2) =
                *reinterpret_cast<const __nv_bfloat162*>(g_M_lo + off);
        }
        #pragma unroll
        for (int i = 0; i < 4; i++) {
            int idx = i * 256 + tid;
            int e = idx >> 5, n4 = (idx & 31) * 4;
            size_t off = ((size_t)b * CB + e0 + e) * NN + n_base + n4;
            *reinterpret_cast<uint2*>(Vhi + e * XS + n4) =
                *reinterpret_cast<const uint2*>(g_v_hi + off);
            *reinterpret_cast<uint2*>(Vlo + e * XS + n4) =
                *reinterpret_cast<const uint2*>(g_v_lo + off);
        }
        __syncthreads();

        #pragma unroll
        for (int ks = 0; ks < 2; ks++) {
            const int kk = ks * 16;
            uint32_t Ah[2][4], Al[2][4];
            #pragma unroll
            for (int fm = 0; fm < 2; fm++) {
                int mrow = wm * 32 + fm * 16 + (g & 1) * 8 + r;
                int kcol = kk + (g >> 1) * 8;
                ldm4(Ah[fm], sptr(Mhi + mrow * MS + kcol));
                ldm4(Al[fm], sptr(Mlo + mrow * MS + kcol));
            }
            #pragma unroll
            for (int h = 0; h < 2; h++) {
                uint32_t Bh[4][2], Bl[4][2];
                #pragma unroll
                for (int nt = 0; nt < 2; nt++) {
                    int row = kk + (g & 1) * 8 + r;
                    int col = wn * 64 + h * 32 + nt * 16 + (g >> 1) * 8;
                    uint32_t t[4];
                    ldm4t(t, sptr(Vhi + row * XS + col));
                    Bh[nt*2][0]=t[0]; Bh[nt*2][1]=t[1]; Bh[nt*2+1][0]=t[2]; Bh[nt*2+1][1]=t[3];
                    ldm4t(t, sptr(Vlo + row * XS + col));
                    Bl[nt*2][0]=t[0]; Bl[nt*2][1]=t[1]; Bl[nt*2+1][0]=t[2]; Bl[nt*2+1][1]=t[3];
                }
                #pragma unroll
                for (int fm = 0; fm < 2; fm++) {
                    #pragma unroll
                    for (int fn4 = 0; fn4 < 4; fn4++) {
                        float* c = acc[fm][h * 4 + fn4];
                        mma16816(c, Ah[fm], Bh[fn4]);
                        mma16816(c, Ah[fm], Bl[fn4]);
                        mma16816(c, Al[fm], Bh[fn4]);
                    }
                }
            }
        }
        __syncthreads();
    }

    // ---- smem-staged coalesced epilogue: two chunks of 64 rows ----
    float* S = reinterpret_cast<float*>(smem);   // [64][136] fp32 = 34816 B
    const float gm = gamma[0];
    #pragma unroll
    for (int cc = 0; cc < 2; cc++) {
        if ((wm >> 1) == cc) {
            #pragma unroll
            for (int fm = 0; fm < 2; fm++) {
                int sr = (wm & 1) * 32 + fm * 16 + q_r;
                #pragma unroll
                for (int fn = 0; fn < 8; fn++) {
                    int sc = wn * 64 + fn * 8 + q_c;
                    *reinterpret_cast<float2*>(&S[sr * 136 + sc]) =
                        make_float2(acc[fm][fn][0], acc[fm][fn][1]);
                    *reinterpret_cast<float2*>(&S[(sr + 8) * 136 + sc]) =
                        make_float2(acc[fm][fn][2], acc[fm][fn][3]);
                }
            }
        }
        __syncthreads();
        #pragma unroll
        for (int i = 0; i < 8; i++) {
            int idx = i * 256 + tid;
            int row = idx >> 5, n4 = (idx & 31) * 4;
            int c = cb0 + cc * 64 + row;
            float gb = gm * b_o[c];
            size_t off = ((size_t)b * CC + c) * NN + n_base + n4;
            float4 xv = *reinterpret_cast<const float4*>(x + off);
            float4 sv = *reinterpret_cast<const float4*>(&S[row * 136 + n4]);
            float4 rv = {sv.x + gb + xv.x, sv.y + gb + xv.y,
                         sv.z + gb + xv.z, sv.w + gb + xv.w};
            *reinterpret_cast<float4*>(out + off) = rv;
        }
        __syncthreads();
    }
}

// ---------------------------------------------------------------------------
// Launch
// ---------------------------------------------------------------------------
extern "C" void kernel_launch(void* const* d_in, const int* in_sizes, int n_in,
                              void* d_out, int out_size)
{
    const float* x     = (const float*)d_in[0];
    const float* w_q   = (const float*)d_in[1];
    const float* b_q   = (const float*)d_in[2];
    const float* w_k   = (const float*)d_in[3];
    const float* b_k   = (const float*)d_in[4];
    const float* w_v   = (const float*)d_in[5];
    const float* b_v   = (const float*)d_in[6];
    const float* w_o   = (const float*)d_in[7];
    const float* b_o   = (const float*)d_in[8];
    const float* gamma = (const float*)d_in[9];
    float* out = (float*)d_out;

    prep_w_kernel<<<192, 512>>>(w_q, w_k, w_v);
    qkv_logits_kernel<<<dim3(NT, BB), 512>>>(x, b_q, b_k, b_v);
    softmax_m_kernel<<<dim3(BB, 4), 256>>>(w_o, gamma);
    out_kernel<<<dim3(NN / 128, CC / 128, BB), 256>>>(x, b_o, gamma, out);
}

// round 6
// speedup vs baseline: 2.2125x; 1.0317x over previous
#include <cuda_runtime.h>
#include <cuda_bf16.h>
#include <math.h>
#include <stdint.h>

// Problem constants
#define BB 16
#define CC 512
#define CB 64
#define NN 4096
#define NT 32    // n-tiles of 128 per batch

// ---------------------------------------------------------------------------
// Scratch (static __device__ arrays — no runtime allocation)
// ---------------------------------------------------------------------------
__device__ __align__(16) __nv_bfloat16 g_v_hi[BB * CB * NN];   // 8 MB
__device__ __align__(16) __nv_bfloat16 g_v_lo[BB * CB * NN];   // 8 MB
__device__ float g_lp[BB * NT * CB * CB];                      // 8 MB
__device__ __align__(16) __nv_bfloat16 g_M_hi[BB * CC * CB];   // 1 MB
__device__ __align__(16) __nv_bfloat16 g_M_lo[BB * CC * CB];   // 1 MB
// Pre-split stacked QKV weights, chunk-major: [16 kc][192 m][32 k]
__device__ __align__(16) __nv_bfloat16 g_w_hi[16 * 192 * 32];
__device__ __align__(16) __nv_bfloat16 g_w_lo[16 * 192 * 32];

// ---------------------------------------------------------------------------
// MMA / async helpers
// ---------------------------------------------------------------------------
__device__ __forceinline__ uint32_t sptr(const void* p) {
    return (uint32_t)__cvta_generic_to_shared(p);
}
__device__ __forceinline__ void ldm4(uint32_t* r, uint32_t a) {
    asm volatile("ldmatrix.sync.aligned.m8n8.x4.shared.b16 {%0,%1,%2,%3}, [%4];"
        : "=r"(r[0]), "=r"(r[1]), "=r"(r[2]), "=r"(r[3]) : "r"(a));
}
__device__ __forceinline__ void ldm4t(uint32_t* r, uint32_t a) {
    asm volatile("ldmatrix.sync.aligned.m8n8.x4.trans.shared.b16 {%0,%1,%2,%3}, [%4];"
        : "=r"(r[0]), "=r"(r[1]), "=r"(r[2]), "=r"(r[3]) : "r"(a));
}
__device__ __forceinline__ void mma16816(float* c, const uint32_t* a, const uint32_t* b) {
    asm volatile("mma.sync.aligned.m16n8k16.row.col.f32.bf16.bf16.f32 "
        "{%0,%1,%2,%3}, {%4,%5,%6,%7}, {%8,%9}, {%0,%1,%2,%3};"
        : "+f"(c[0]), "+f"(c[1]), "+f"(c[2]), "+f"(c[3])
        : "r"(a[0]), "r"(a[1]), "r"(a[2]), "r"(a[3]), "r"(b[0]), "r"(b[1]));
}
__device__ __forceinline__ void split2(float v, __nv_bfloat16& h, __nv_bfloat16& l) {
    h = __float2bfloat16_rn(v);
    l = __float2bfloat16_rn(v - __bfloat162float(h));
}
__device__ __forceinline__ void cpasync16(uint32_t dst, const void* src) {
    asm volatile("cp.async.cg.shared.global [%0], [%1], 16;" :: "r"(dst), "l"(src));
}
#define CP_COMMIT() asm volatile("cp.async.commit_group;")
#define CP_WAIT0()  asm volatile("cp.async.wait_group 0;" ::: "memory")

#define WS 40     // W smem row stride (bf16)
#define XS 136    // X/V smem row stride (bf16)
#define QS 72     // Q/K smem row stride (bf16)
#define MS 40     // M smem row stride (bf16)

// qkv dynamic smem byte layout:
//   Whi0 0        Wlo0 15360   Whi1 30720   Wlo1 46080
//   Xhi0 61440    Xlo0 70144   Xhi1 78848   Xlo1 87552
//   Xraw0 96256   Xraw1 112640   total 129024
#define QKV_SMEM 129024

// ---------------------------------------------------------------------------
// Kernel 0: pre-split stacked W into bf16 hi/lo planes, chunk-major layout.
// ---------------------------------------------------------------------------
__global__ __launch_bounds__(512) void prep_w_kernel(
    const float* __restrict__ wq, const float* __restrict__ wk,
    const float* __restrict__ wv)
{
    const int m = blockIdx.x, t = threadIdx.x;
    const float* src = (m < 64) ? (wq + m * CC)
                     : (m < 128) ? (wk + (m - 64) * CC)
                                 : (wv + (m - 128) * CC);
    float v = src[t];
    __nv_bfloat16 h, l;
    split2(v, h, l);
    int dst = (t >> 5) * (192 * 32) + m * 32 + (t & 31);
    g_w_hi[dst] = h;
    g_w_lo[dst] = l;
}

// ---------------------------------------------------------------------------
// Kernel 1: fused QKV projection (bf16x3 mma) + logits partial (bf16x3 mma).
// grid (32, 16), block 256 (8 warps).  Warp grid 2m x 4n, warp tile 96x32.
// cp.async double-buffered W (pre-split) and X (raw fp32, split on-chip).
// ---------------------------------------------------------------------------
__global__ __launch_bounds__(256, 1) void qkv_logits_kernel(
    const float* __restrict__ x,
    const float* __restrict__ bq, const float* __restrict__ bk,
    const float* __restrict__ bv)
{
    extern __shared__ __align__(16) char dsm[];
    __nv_bfloat16* const smb = reinterpret_cast<__nv_bfloat16*>(dsm);

    const int b = blockIdx.y, ntile = blockIdx.x;
    const int n_base = ntile * 128;
    const int tid = threadIdx.x, lane = tid & 31, wid = tid >> 5;
    const int wm = wid >> 2, wn = wid & 3;
    const int g = lane >> 3, r = lane & 7;
    const int q_r = lane >> 2, q_c = (lane & 3) * 2;
    const float* xb = x + (size_t)b * CC * NN;

    const uint32_t sbase = sptr(dsm);
    const uint32_t uWa0 = sbase + ((wm * 96 + (g & 1) * 8 + r) * WS + (g >> 1) * 8) * 2;
    const uint32_t uXb0 = sbase + 61440 + (((g & 1) * 8 + r) * XS + wn * 32 + (g >> 1) * 8) * 2;

    float acc[6][4][4];
    #pragma unroll
    for (int i = 0; i < 6; i++)
        #pragma unroll
        for (int j = 0; j < 4; j++)
            #pragma unroll
            for (int e = 0; e < 4; e++) acc[i][j][e] = 0.f;

    // --- async copy issuers ---
    auto cpW = [&](int kc, int buf) {
        const char* sh = reinterpret_cast<const char*>(g_w_hi) + kc * 12288;
        const char* sl = reinterpret_cast<const char*>(g_w_lo) + kc * 12288;
        uint32_t dst = sbase + buf * 30720;
        #pragma unroll
        for (int i = 0; i < 3; i++) {
            int idx = i * 256 + tid;               // 0..767
            int m = idx >> 2, sg = (idx & 3) * 16; // bytes within row
            cpasync16(dst + m * 80 + sg, sh + m * 64 + sg);
            cpasync16(dst + 15360 + m * 80 + sg, sl + m * 64 + sg);
        }
    };
    auto cpX = [&](int kc, int buf) {
        uint32_t dst = sbase + 96256 + buf * 16384;
        const char* src = reinterpret_cast<const char*>(xb + (size_t)kc * 32 * NN + n_base);
        #pragma unroll
        for (int i = 0; i < 4; i++) {
            int idx = i * 256 + tid;               // 0..1023
            int k = idx >> 5, n4 = (idx & 31) * 4;
            cpasync16(dst + idx * 16, src + ((size_t)k * NN + n4) * 4);
        }
    };

    // prologue
    cpW(0, 0);
    cpX(0, 0);
    CP_COMMIT();

    for (int kc = 0; kc < 16; kc++) {
        const int cur = kc & 1;
        CP_WAIT0();
        __syncthreads();   // chunk kc data ready; all prior compute done
        if (kc < 15) {
            cpW(kc + 1, cur ^ 1);
            cpX(kc + 1, cur ^ 1);
            CP_COMMIT();   // overlaps split + compute below
        }
        // split raw fp32 X chunk -> bf16 hi/lo planes
        {
            const float* Xr = reinterpret_cast<const float*>(dsm + 96256 + cur * 16384);
            __nv_bfloat16* Xh = smb + (61440 + cur * 17408) / 2;
            __nv_bfloat16* Xl = Xh + 4352;
            #pragma unroll
            for (int i = 0; i < 4; i++) {
                int idx = i * 256 + tid;
                int k = idx >> 5, n4 = (idx & 31) * 4;
                float4 v = *reinterpret_cast<const float4*>(Xr + idx * 4);
                __nv_bfloat16 h0, l0, h1, l1, h2, l2, h3, l3;
                split2(v.x, h0, l0); split2(v.y, h1, l1);
                split2(v.z, h2, l2); split2(v.w, h3, l3);
                __nv_bfloat16* dh = Xh + k * XS + n4;
                __nv_bfloat16* dl = Xl + k * XS + n4;
                *reinterpret_cast<__nv_bfloat162*>(dh)     = __nv_bfloat162(h0, h1);
                *reinterpret_cast<__nv_bfloat162*>(dh + 2) = __nv_bfloat162(h2, h3);
                *reinterpret_cast<__nv_bfloat162*>(dl)     = __nv_bfloat162(l0, l1);
                *reinterpret_cast<__nv_bfloat162*>(dl + 2) = __nv_bfloat162(l2, l3);
            }
        }
        __syncthreads();

        const uint32_t uWa = uWa0 + cur * 30720;
        const uint32_t uXb = uXb0 + cur * 17408;
        #pragma unroll
        for (int ks = 0; ks < 2; ks++) {
            uint32_t Bh[4][2], Bl[4][2];
            #pragma unroll
            for (int nt2 = 0; nt2 < 2; nt2++) {
                uint32_t t[4];
                ldm4t(t, uXb + ks * 4352 + nt2 * 32);
                Bh[nt2*2][0]=t[0]; Bh[nt2*2][1]=t[1]; Bh[nt2*2+1][0]=t[2]; Bh[nt2*2+1][1]=t[3];
                ldm4t(t, uXb + 8704 + ks * 4352 + nt2 * 32);
                Bl[nt2*2][0]=t[0]; Bl[nt2*2][1]=t[1]; Bl[nt2*2+1][0]=t[2]; Bl[nt2*2+1][1]=t[3];
            }
            #pragma unroll
            for (int fm = 0; fm < 6; fm++) {
                uint32_t Ah[4], Al[4];
                ldm4(Ah, uWa + fm * 1280 + ks * 32);
                ldm4(Al, uWa + 15360 + fm * 1280 + ks * 32);
                #pragma unroll
                for (int fn = 0; fn < 4; fn++) {
                    mma16816(acc[fm][fn], Ah, Bh[fn]);
                    mma16816(acc[fm][fn], Ah, Bl[fn]);
                    mma16816(acc[fm][fn], Al, Bh[fn]);
                }
            }
        }
        // no trailing sync needed: next iter's post-wait sync guards reuse
    }

    // ---- v rows (m 128..191 = wm==1, fm 2..5): bias, split, -> global ----
    if (wm == 1) {
        #pragma unroll
        for (int fm = 2; fm < 6; fm++) {
            int cb0 = (fm - 2) * 16 + q_r;
            float bv0 = bv[cb0], bv8 = bv[cb0 + 8];
            #pragma unroll
            for (int fn = 0; fn < 4; fn++) {
                int n = n_base + wn * 32 + fn * 8 + q_c;
                float v0 = acc[fm][fn][0] + bv0, v1 = acc[fm][fn][1] + bv0;
                float v2 = acc[fm][fn][2] + bv8, v3 = acc[fm][fn][3] + bv8;
                __nv_bfloat16 h0, l0, h1, l1, h2, l2, h3, l3;
                split2(v0, h0, l0); split2(v1, h1, l1);
                split2(v2, h2, l2); split2(v3, h3, l3);
                size_t o0 = ((size_t)b * CB + cb0) * NN + n;
                size_t o8 = o0 + (size_t)8 * NN;
                *reinterpret_cast<__nv_bfloat162*>(g_v_hi + o0) = __nv_bfloat162(h0, h1);
                *reinterpret_cast<__nv_bfloat162*>(g_v_lo + o0) = __nv_bfloat162(l0, l1);
                *reinterpret_cast<__nv_bfloat162*>(g_v_hi + o8) = __nv_bfloat162(h2, h3);
                *reinterpret_cast<__nv_bfloat162*>(g_v_lo + o8) = __nv_bfloat162(l2, l3);
            }
        }
    }

    // ---- logits over two 64-n halves; q,k re-split -> bf16x3 mma ----
    __nv_bfloat16* Qhi = smb;
    __nv_bfloat16* Qlo = smb + 4608;
    __nv_bfloat16* Khi = smb + 9216;
    __nv_bfloat16* Klo = smb + 13824;

    float lacc[4][4];
    #pragma unroll
    for (int i = 0; i < 4; i++)
        #pragma unroll
        for (int j = 0; j < 4; j++) lacc[i][j] = 0.f;
    const int wml = wid >> 1, wnl = wid & 1;

    #pragma unroll
    for (int p = 0; p < 2; p++) {
        __syncthreads();   // prior smem consumers done
        if ((wn >> 1) == p) {
            #pragma unroll
            for (int fm = 0; fm < 6; fm++) {
                int m0 = wm * 96 + fm * 16 + q_r;
                if (m0 < 128) {
                    bool isq = (m0 < 64);
                    int r0 = isq ? m0 : (m0 - 64);
                    float bb0 = isq ? bq[m0] : bk[m0 - 64];
                    float bb8 = isq ? bq[m0 + 8] : bk[m0 - 56];
                    __nv_bfloat16* Phi = isq ? Qhi : Khi;
                    __nv_bfloat16* Plo = isq ? Qlo : Klo;
                    #pragma unroll
                    for (int fn = 0; fn < 4; fn++) {
                        int col = wn * 32 + fn * 8 + q_c - p * 64;
                        float v0 = acc[fm][fn][0] + bb0, v1 = acc[fm][fn][1] + bb0;
                        float v2 = acc[fm][fn][2] + bb8, v3 = acc[fm][fn][3] + bb8;
                        __nv_bfloat16 h0, l0, h1, l1, h2, l2, h3, l3;
                        split2(v0, h0, l0); split2(v1, h1, l1);
                        split2(v2, h2, l2); split2(v3, h3, l3);
                        *reinterpret_cast<__nv_bfloat162*>(Phi + r0 * QS + col)       = __nv_bfloat162(h0, h1);
                        *reinterpret_cast<__nv_bfloat162*>(Plo + r0 * QS + col)       = __nv_bfloat162(l0, l1);
                        *reinterpret_cast<__nv_bfloat162*>(Phi + (r0 + 8) * QS + col) = __nv_bfloat162(h2, h3);
                        *reinterpret_cast<__nv_bfloat162*>(Plo + (r0 + 8) * QS + col) = __nv_bfloat162(l2, l3);
                    }
                }
            }
        }
        __syncthreads();
        #pragma unroll
        for (int ks = 0; ks < 4; ks++) {
            const int kk = ks * 16;
            uint32_t Ah[4], Al[4];
            {
                int row = wml * 16 + (g & 1) * 8 + r;
                int col = kk + (g >> 1) * 8;
                ldm4(Ah, sptr(Qhi + row * QS + col));
                ldm4(Al, sptr(Qlo + row * QS + col));
            }
            #pragma unroll
            for (int dt = 0; dt < 2; dt++) {
                int drow = wnl * 32 + dt * 16 + (g >> 1) * 8 + r;
                int dcol = kk + (g & 1) * 8;
                uint32_t Bh_[4], Bl_[4];
                ldm4(Bh_, sptr(Khi + drow * QS + dcol));
                ldm4(Bl_, sptr(Klo + drow * QS + dcol));
                mma16816(lacc[dt*2],     Ah, Bh_ + 0);
                mma16816(lacc[dt*2],     Ah, Bl_ + 0);
                mma16816(lacc[dt*2],     Al, Bh_ + 0);
                mma16816(lacc[dt*2 + 1], Ah, Bh_ + 2);
                mma16816(lacc[dt*2 + 1], Ah, Bl_ + 2);
                mma16816(lacc[dt*2 + 1], Al, Bh_ + 2);
            }
        }
    }

    // ---- write logits partial [64,64] ----
    float* lp = g_lp + (size_t)(b * NT + ntile) * (CB * CB);
    #pragma unroll
    for (int df = 0; df < 4; df++) {
        int cr = wml * 16 + q_r;
        int dc = wnl * 32 + df * 8 + q_c;
        lp[cr * CB + dc]           = lacc[df][0];
        lp[cr * CB + dc + 1]       = lacc[df][1];
        lp[(cr + 8) * CB + dc]     = lacc[df][2];
        lp[(cr + 8) * CB + dc + 1] = lacc[df][3];
    }
}

// ---------------------------------------------------------------------------
// Kernel 2: reduce partials -> softmax -> M = gamma*(w_o@attn) -> bf16 hi/lo.
// ---------------------------------------------------------------------------
__global__ __launch_bounds__(256) void softmax_m_kernel(
    const float* __restrict__ w_o, const float* __restrict__ gamma)
{
    __shared__ float L[CB * CB];
    const int b = blockIdx.x, cbase = blockIdx.y * 128, tid = threadIdx.x;

    #pragma unroll
    for (int t = 0; t < 16; t++) {
        int idx = tid + 256 * t;
        float s0 = 0.f;
        #pragma unroll 8
        for (int s = 0; s < NT; s++)
            s0 += g_lp[(size_t)(b * NT + s) * (CB * CB) + idx];
        L[idx] = s0;
    }
    __syncthreads();

    if (tid < CB) {
        float* row = &L[tid * CB];
        float mx = row[0];
        #pragma unroll
        for (int d = 1; d < CB; d++) mx = fmaxf(mx, row[d]);
        float sum = 0.f;
        #pragma unroll
        for (int d = 0; d < CB; d++) { float e = expf(row[d] - mx); row[d] = e; sum += e; }
        float inv = 1.f / sum;
        #pragma unroll
        for (int d = 0; d < CB; d++) row[d] *= inv;
    }
    __syncthreads();

    const float gm = gamma[0];
    for (int o = tid; o < 128 * CB; o += 256) {
        int c = cbase + (o >> 6), d = o & 63;
        float sum = 0.f;
        #pragma unroll
        for (int e = 0; e < CB; e++)
            sum = fmaf(w_o[c * CB + e], L[e * CB + d], sum);
        float mval = gm * sum;
        __nv_bfloat16 h, l;
        split2(mval, h, l);
        size_t off = ((size_t)b * CC + c) * CB + d;
        g_M_hi[off] = h;
        g_M_lo[off] = l;
    }
}

// ---------------------------------------------------------------------------
// Kernel 3: out = M@v (bf16x3 mma) + gamma*b_o + x.  (unchanged from R5)
// ---------------------------------------------------------------------------
__global__ __launch_bounds__(256, 2) void out_kernel(
    const float* __restrict__ x,
    const float* __restrict__ b_o, const float* __restrict__ gamma,
    float* __restrict__ out)
{
    __shared__ __align__(16) __nv_bfloat16 smem[18944];
    __nv_bfloat16* Mhi = smem;            // [128][40]
    __nv_bfloat16* Mlo = smem + 5120;
    __nv_bfloat16* Vhi = smem + 10240;    // [32][136]
    __nv_bfloat16* Vlo = smem + 14592;

    const int b = blockIdx.z, cb0 = blockIdx.y * 128, n_base = blockIdx.x * 128;
    const int tid = threadIdx.x, lane = tid & 31, wid = tid >> 5;
    const int wm = wid >> 1, wn = wid & 1;
    const int g = lane >> 3, r = lane & 7;
    const int q_r = lane >> 2, q_c = (lane & 3) * 2;

    float acc[2][8][4];
    #pragma unroll
    for (int i = 0; i < 2; i++)
        #pragma unroll
        for (int j = 0; j < 8; j++)
            #pragma unroll
            for (int e = 0; e < 4; e++) acc[i][j][e] = 0.f;

    #pragma unroll
    for (int ec = 0; ec < 2; ec++) {
        const int e0 = ec * 32;
        #pragma unroll
        for (int i = 0; i < 8; i++) {
            int idx = i * 256 + tid;
            int c = idx >> 4, e2 = (idx & 15) * 2;
            size_t off = ((size_t)b * CC + cb0 + c) * CB + e0 + e2;
            *reinterpret_cast<__nv_bfloat162*>(Mhi + c * MS + e2) =
                *reinterpret_cast<const __nv_bfloat162*>(g_M_hi + off);
            *reinterpret_cast<__nv_bfloat162*>(Mlo + c * MS + e2) =
                *reinterpret_cast<const __nv_bfloat162*>(g_M_lo + off);
        }
        #pragma unroll
        for (int i = 0; i < 4; i++) {
            int idx = i * 256 + tid;
            int e = idx >> 5, n4 = (idx & 31) * 4;
            size_t off = ((size_t)b * CB + e0 + e) * NN + n_base + n4;
            *reinterpret_cast<uint2*>(Vhi + e * XS + n4) =
                *reinterpret_cast<const uint2*>(g_v_hi + off);
            *reinterpret_cast<uint2*>(Vlo + e * XS + n4) =
                *reinterpret_cast<const uint2*>(g_v_lo + off);
        }
        __syncthreads();

        #pragma unroll
        for (int ks = 0; ks < 2; ks++) {
            const int kk = ks * 16;
            uint32_t Ah[2][4], Al[2][4];
            #pragma unroll
            for (int fm = 0; fm < 2; fm++) {
                int mrow = wm * 32 + fm * 16 + (g & 1) * 8 + r;
                int kcol = kk + (g >> 1) * 8;
                ldm4(Ah[fm], sptr(Mhi + mrow * MS + kcol));
                ldm4(Al[fm], sptr(Mlo + mrow * MS + kcol));
            }
            #pragma unroll
            for (int h = 0; h < 2; h++) {
                uint32_t Bh[4][2], Bl[4][2];
                #pragma unroll
                for (int nt = 0; nt < 2; nt++) {
                    int row = kk + (g & 1) * 8 + r;
                    int col = wn * 64 + h * 32 + nt * 16 + (g >> 1) * 8;
                    uint32_t t[4];
                    ldm4t(t, sptr(Vhi + row * XS + col));
                    Bh[nt*2][0]=t[0]; Bh[nt*2][1]=t[1]; Bh[nt*2+1][0]=t[2]; Bh[nt*2+1][1]=t[3];
                    ldm4t(t, sptr(Vlo + row * XS + col));
                    Bl[nt*2][0]=t[0]; Bl[nt*2][1]=t[1]; Bl[nt*2+1][0]=t[2]; Bl[nt*2+1][1]=t[3];
                }
                #pragma unroll
                for (int fm = 0; fm < 2; fm++) {
                    #pragma unroll
                    for (int fn4 = 0; fn4 < 4; fn4++) {
                        float* c = acc[fm][h * 4 + fn4];
                        mma16816(c, Ah[fm], Bh[fn4]);
                        mma16816(c, Ah[fm], Bl[fn4]);
                        mma16816(c, Al[fm], Bh[fn4]);
                    }
                }
            }
        }
        __syncthreads();
    }

    // ---- smem-staged coalesced epilogue: two chunks of 64 rows ----
    float* S = reinterpret_cast<float*>(smem);   // [64][136] fp32
    const float gm = gamma[0];
    #pragma unroll
    for (int cc = 0; cc < 2; cc++) {
        if ((wm >> 1) == cc) {
            #pragma unroll
            for (int fm = 0; fm < 2; fm++) {
                int sr = (wm & 1) * 32 + fm * 16 + q_r;
                #pragma unroll
                for (int fn = 0; fn < 8; fn++) {
                    int sc = wn * 64 + fn * 8 + q_c;
                    *reinterpret_cast<float2*>(&S[sr * 136 + sc]) =
                        make_float2(acc[fm][fn][0], acc[fm][fn][1]);
                    *reinterpret_cast<float2*>(&S[(sr + 8) * 136 + sc]) =
                        make_float2(acc[fm][fn][2], acc[fm][fn][3]);
                }
            }
        }
        __syncthreads();
        #pragma unroll
        for (int i = 0; i < 8; i++) {
            int idx = i * 256 + tid;
            int row = idx >> 5, n4 = (idx & 31) * 4;
            int c = cb0 + cc * 64 + row;
            float gb = gm * b_o[c];
            size_t off = ((size_t)b * CC + c) * NN + n_base + n4;
            float4 xv = *reinterpret_cast<const float4*>(x + off);
            float4 sv = *reinterpret_cast<const float4*>(&S[row * 136 + n4]);
            float4 rv = {sv.x + gb + xv.x, sv.y + gb + xv.y,
                         sv.z + gb + xv.z, sv.w + gb + xv.w};
            *reinterpret_cast<float4*>(out + off) = rv;
        }
        __syncthreads();
    }
}

// ---------------------------------------------------------------------------
// Launch
// ---------------------------------------------------------------------------
extern "C" void kernel_launch(void* const* d_in, const int* in_sizes, int n_in,
                              void* d_out, int out_size)
{
    const float* x     = (const float*)d_in[0];
    const float* w_q   = (const float*)d_in[1];
    const float* b_q   = (const float*)d_in[2];
    const float* w_k   = (const float*)d_in[3];
    const float* b_k   = (const float*)d_in[4];
    const float* w_v   = (const float*)d_in[5];
    const float* b_v   = (const float*)d_in[6];
    const float* w_o   = (const float*)d_in[7];
    const float* b_o   = (const float*)d_in[8];
    const float* gamma = (const float*)d_in[9];
    float* out = (float*)d_out;

    cudaFuncSetAttribute(qkv_logits_kernel,
                         cudaFuncAttributeMaxDynamicSharedMemorySize, QKV_SMEM);

    prep_w_kernel<<<192, 512>>>(w_q, w_k, w_v);
    qkv_logits_kernel<<<dim3(NT, BB), 256, QKV_SMEM>>>(x, b_q, b_k, b_v);
    softmax_m_kernel<<<dim3(BB, 4), 256>>>(w_o, gamma);
    out_kernel<<<dim3(NN / 128, CC / 128, BB), 256>>>(x, b_o, gamma, out);
}